// round 11
// baseline (speedup 1.0000x reference)
#include <cuda_runtime.h>
#include <cuda_bf16.h>

#define DH 128
#define N_NODES_MAX 50000
#define N_EDGES_MAX 1600000
#define N_GRAPHS_MAX 64
#define NPB 128      // nodes per block in GEMM (16 per warp)
#define AST 130      // Ash transposed stride (pad; 8B-aligned rows)

// ---------------- scratch (device globals: allocation-free) ----------------
__device__ float g_bufA[N_NODES_MAX * DH];           // aggregation result (fp32, GEMM input)
__device__ __nv_bfloat16 g_xb[N_NODES_MAX * DH];     // x * dis[n], bf16 (layer-1 gather src)
__device__ __nv_bfloat16 g_h1b[N_NODES_MAX * DH];    // h1 * dis[n], bf16 (layer-2 gather src)
__device__ float g_dis[N_NODES_MAX];                 // deg^{-1/2}
__device__ int   g_count[N_NODES_MAX];               // in-degree (zeroed by k_scan after use)
__device__ int   g_off[N_NODES_MAX + 1];             // CSR offsets (by dst)
__device__ int   g_cur[N_NODES_MAX];                 // build cursors
__device__ int   g_srcs[N_EDGES_MAX];                // CSR: src node per slot
__device__ float g_pooled[N_GRAPHS_MAX * DH];
__device__ float g_cnt[N_GRAPHS_MAX];

__device__ __forceinline__ void red_add_v4(float4* addr, float4 v) {
    asm volatile("red.global.add.v4.f32 [%0], {%1, %2, %3, %4};"
                 :: "l"(addr), "f"(v.x), "f"(v.y), "f"(v.z), "f"(v.w)
                 : "memory");
}

// f32x2 packed helpers (Blackwell FFMA2 path — PTX-only)
__device__ __forceinline__ unsigned long long pk2(float x, float y) {
    unsigned long long u;
    asm("mov.b64 %0, {%1, %2};" : "=l"(u) : "f"(x), "f"(y));
    return u;
}
__device__ __forceinline__ void upk2(float& x, float& y, unsigned long long u) {
    asm("mov.b64 {%0, %1}, %2;" : "=f"(x), "=f"(y) : "l"(u));
}
__device__ __forceinline__ unsigned long long fma2(unsigned long long a,
                                                   unsigned long long b,
                                                   unsigned long long c) {
    unsigned long long d;
    asm("fma.rn.f32x2 %0, %1, %2, %3;" : "=l"(d) : "l"(a), "l"(b), "l"(c));
    return d;
}

// ---------------- histogram (int4 vectorized, 4 edges/thread) ----------------
// g_count is zero on entry: .bss zero-init on first call; k_scan re-zeros after use.
__global__ void k_hist4(const int4* __restrict__ dst4, int nQ) {
    int t = blockIdx.x * blockDim.x + threadIdx.x;
    if (t >= nQ) return;
    int4 d = __ldg(&dst4[t]);
    atomicAdd(&g_count[d.x], 1);
    atomicAdd(&g_count[d.y], 1);
    atomicAdd(&g_count[d.z], 1);
    atomicAdd(&g_count[d.w], 1);
}
__global__ void k_hist_s(const int* __restrict__ dst, int nE) {   // scalar fallback
    int t = blockIdx.x * blockDim.x + threadIdx.x;
    int e0 = t * 4;
#pragma unroll
    for (int j = 0; j < 4; j++)
        if (e0 + j < nE) atomicAdd(&g_count[dst[e0 + j]], 1);
}

// ------- single-block exclusive scan + dis; re-zeros g_count for next call -----
__global__ void __launch_bounds__(1024, 1) k_scan(int nN) {
    __shared__ int sums[1024];
    int t = threadIdx.x;
    int C = (nN + 1023) >> 10;
    int lo = t * C;
    int hi = min(lo + C, nN);

    int s = 0;
    for (int i = lo; i < hi; i++) s += g_count[i];
    sums[t] = s;
    __syncthreads();

    for (int off = 1; off < 1024; off <<= 1) {
        int u = (t >= off) ? sums[t - off] : 0;
        __syncthreads();
        sums[t] += u;
        __syncthreads();
    }

    int run = sums[t] - s;
    for (int i = lo; i < hi; i++) {
        g_off[i] = run;
        g_cur[i] = run;
        int c = g_count[i];
        g_count[i] = 0;                       // restore invariant for next launch
        g_dis[i] = (c > 0) ? rsqrtf((float)c) : 0.f;
        run += c;
    }
    if (t == 1023) g_off[nN] = sums[1023];
}

// -------- fused: CSR build (blocks [0,Bb)) + x pre-scale (blocks [Bb,..)) ------
// build: int4 vectorized permute of edges into dst-grouped order.
// scale: xb[n] = bf16(x[n]*dis[n]); also zeros pooled/cnt.
__global__ void k_build_scale(const int4* __restrict__ src4, const int4* __restrict__ dst4,
                              int nQ, const float4* __restrict__ x, int nN, int Bb) {
    if ((int)blockIdx.x < Bb) {
        int t = blockIdx.x * blockDim.x + threadIdx.x;
        if (t >= nQ) return;
        int4 d = __ldg(&dst4[t]);
        int4 s = __ldg(&src4[t]);
        int p0 = atomicAdd(&g_cur[d.x], 1);
        int p1 = atomicAdd(&g_cur[d.y], 1);
        int p2 = atomicAdd(&g_cur[d.z], 1);
        int p3 = atomicAdd(&g_cur[d.w], 1);
        g_srcs[p0] = s.x; g_srcs[p1] = s.y; g_srcs[p2] = s.z; g_srcs[p3] = s.w;
    } else {
        int idx = (blockIdx.x - Bb) * blockDim.x + threadIdx.x;
        if (idx < N_GRAPHS_MAX * DH) g_pooled[idx] = 0.f;
        if (idx < N_GRAPHS_MAX) g_cnt[idx] = 0.f;
        int n = idx >> 5;
        if (n >= nN) return;
        int lane = idx & 31;
        float d = g_dis[n];
        float4 v = x[(size_t)n * 32 + lane];
        __nv_bfloat162 p0 = __float22bfloat162_rn(make_float2(v.x * d, v.y * d));
        __nv_bfloat162 p1 = __float22bfloat162_rn(make_float2(v.z * d, v.w * d));
        uint2 u;
        u.x = *reinterpret_cast<unsigned*>(&p0);
        u.y = *reinterpret_cast<unsigned*>(&p1);
        reinterpret_cast<uint2*>(g_xb)[(size_t)n * 32 + lane] = u;
    }
}
// scalar-build fallback (nE % 4 != 0)
__global__ void k_build_scale_s(const int* __restrict__ src, const int* __restrict__ dst,
                                int nE, const float4* __restrict__ x, int nN, int Bb) {
    if ((int)blockIdx.x < Bb) {
        int t = blockIdx.x * blockDim.x + threadIdx.x;
        int e0 = t * 4;
        for (int j = 0; j < 4 && e0 + j < nE; j++) {
            int pos = atomicAdd(&g_cur[dst[e0 + j]], 1);
            g_srcs[pos] = src[e0 + j];
        }
    } else {
        int idx = (blockIdx.x - Bb) * blockDim.x + threadIdx.x;
        if (idx < N_GRAPHS_MAX * DH) g_pooled[idx] = 0.f;
        if (idx < N_GRAPHS_MAX) g_cnt[idx] = 0.f;
        int n = idx >> 5;
        if (n >= nN) return;
        int lane = idx & 31;
        float d = g_dis[n];
        float4 v = x[(size_t)n * 32 + lane];
        __nv_bfloat162 p0 = __float22bfloat162_rn(make_float2(v.x * d, v.y * d));
        __nv_bfloat162 p1 = __float22bfloat162_rn(make_float2(v.z * d, v.w * d));
        uint2 u;
        u.x = *reinterpret_cast<unsigned*>(&p0);
        u.y = *reinterpret_cast<unsigned*>(&p1);
        reinterpret_cast<uint2*>(g_xb)[(size_t)n * 32 + lane] = u;
    }
}

// ---------------- gather: bufA[n] = dis[n] * sum_{s in in(n)} feat_pre[s] ------
// 2 nodes per warp: 16 lanes per node, one uint4 (8 bf16) per lane per edge.
__device__ __forceinline__ void acc8(float* acc, uint4 u) {
    float2 f;
    f = __bfloat1622float2(*reinterpret_cast<__nv_bfloat162*>(&u.x));
    acc[0] += f.x; acc[1] += f.y;
    f = __bfloat1622float2(*reinterpret_cast<__nv_bfloat162*>(&u.y));
    acc[2] += f.x; acc[3] += f.y;
    f = __bfloat1622float2(*reinterpret_cast<__nv_bfloat162*>(&u.z));
    acc[4] += f.x; acc[5] += f.y;
    f = __bfloat1622float2(*reinterpret_cast<__nv_bfloat162*>(&u.w));
    acc[6] += f.x; acc[7] += f.y;
}

__global__ void __launch_bounds__(256) k_gather(int use_x, int nN) {
    int idx = blockIdx.x * blockDim.x + threadIdx.x;
    int n = idx >> 4;
    if (n >= nN) return;
    int lane = idx & 15;

    const uint4* feat = reinterpret_cast<const uint4*>(use_x ? g_xb : g_h1b);

    int b = g_off[n], e = g_off[n + 1];
    float acc[8] = {0.f, 0.f, 0.f, 0.f, 0.f, 0.f, 0.f, 0.f};

    int i = b;
    for (; i + 8 <= e; i += 8) {
        int s[8];
#pragma unroll
        for (int j = 0; j < 8; j++) s[j] = __ldcs(&g_srcs[i + j]);
        uint4 u[8];
#pragma unroll
        for (int j = 0; j < 8; j++) u[j] = __ldg(&feat[(size_t)s[j] * 16 + lane]);
#pragma unroll
        for (int j = 0; j < 8; j++) acc8(acc, u[j]);
    }
    for (; i + 4 <= e; i += 4) {
        int s0 = __ldcs(&g_srcs[i]),     s1 = __ldcs(&g_srcs[i + 1]);
        int s2 = __ldcs(&g_srcs[i + 2]), s3 = __ldcs(&g_srcs[i + 3]);
        uint4 u0 = __ldg(&feat[(size_t)s0 * 16 + lane]);
        uint4 u1 = __ldg(&feat[(size_t)s1 * 16 + lane]);
        uint4 u2 = __ldg(&feat[(size_t)s2 * 16 + lane]);
        uint4 u3 = __ldg(&feat[(size_t)s3 * 16 + lane]);
        acc8(acc, u0); acc8(acc, u1); acc8(acc, u2); acc8(acc, u3);
    }
    for (; i < e; i++) {
        int s = __ldcs(&g_srcs[i]);
        uint4 u = __ldg(&feat[(size_t)s * 16 + lane]);
        acc8(acc, u);
    }

    float dn = g_dis[n];
#pragma unroll
    for (int j = 0; j < 8; j++) acc[j] *= dn;

    float4* orow = reinterpret_cast<float4*>(&g_bufA[(size_t)n * DH + lane * 8]);
    orow[0] = make_float4(acc[0], acc[1], acc[2], acc[3]);
    orow[1] = make_float4(acc[4], acc[5], acc[6], acc[7]);
}

// ---------------- GEMM + bias + ReLU (FFMA2, 16 nodes per warp) ----------------
// 256 threads = 8 warps; warp owns 16 nodes = 8 node-pairs; lane owns 4 cols.
// One W LDS.128 per kk amortized over 16 nodes -> FFMA2-issue-bound.
// mode 0: write bf16(relu(.)*dis[n]) to g_h1b                 (layer 1)
// mode 1: fused pooling — red_add relu(.) into g_pooled[gid]  (layer 2)
__global__ void __launch_bounds__(256, 2)
k_gemm_relu(const float* __restrict__ W, const float* __restrict__ b,
            const int* __restrict__ gid, int nN, int mode) {
    __shared__ float Wsh[32 * DH];       // 16 KB: W rows k0..k0+31
    __shared__ float Ash[32 * AST];      // 16.6 KB: A chunk TRANSPOSED [kk][node]
    __shared__ float bsh[DH];

    const float* A = g_bufA;

    int tid = threadIdx.x;
    int node0 = blockIdx.x * NPB;
    if (tid < DH / 4)
        reinterpret_cast<float4*>(bsh)[tid] = reinterpret_cast<const float4*>(b)[tid];

    int warp = tid >> 5, lane = tid & 31;

    unsigned long long accP[8][4];
#pragma unroll
    for (int p = 0; p < 8; p++)
#pragma unroll
        for (int c = 0; c < 4; c++) accP[p][c] = 0ULL;

    for (int k0 = 0; k0 < DH; k0 += 32) {
        __syncthreads();
#pragma unroll
        for (int i = tid; i < 32 * DH / 4; i += 256)
            reinterpret_cast<float4*>(Wsh)[i] =
                reinterpret_cast<const float4*>(W + (size_t)k0 * DH)[i];
        // A chunk, transposed: Ash[kk][node], 128 nodes x 32 k
#pragma unroll
        for (int i = tid; i < NPB * 8; i += 256) {
            int nl = i >> 3;           // local node 0..127
            int j  = i & 7;            // k sub-chunk of 4
            int n = node0 + nl;
            float4 av = make_float4(0.f, 0.f, 0.f, 0.f);
            if (n < nN)
                av = *reinterpret_cast<const float4*>(&A[(size_t)n * DH + k0 + (j << 2)]);
            Ash[(j * 4 + 0) * AST + nl] = av.x;
            Ash[(j * 4 + 1) * AST + nl] = av.y;
            Ash[(j * 4 + 2) * AST + nl] = av.z;
            Ash[(j * 4 + 3) * AST + nl] = av.w;
        }
        __syncthreads();

#pragma unroll 4
        for (int kk = 0; kk < 32; kk++) {
            float4 w = *reinterpret_cast<const float4*>(&Wsh[kk * DH + lane * 4]);
            unsigned long long wd0 = pk2(w.x, w.x);
            unsigned long long wd1 = pk2(w.y, w.y);
            unsigned long long wd2 = pk2(w.z, w.z);
            unsigned long long wd3 = pk2(w.w, w.w);
            const float* Ar = &Ash[kk * AST + warp * 16];
#pragma unroll
            for (int p = 0; p < 8; p++) {
                unsigned long long pa =
                    *reinterpret_cast<const unsigned long long*>(&Ar[2 * p]);
                accP[p][0] = fma2(pa, wd0, accP[p][0]);
                accP[p][1] = fma2(pa, wd1, accP[p][1]);
                accP[p][2] = fma2(pa, wd2, accP[p][2]);
                accP[p][3] = fma2(pa, wd3, accP[p][3]);
            }
        }
    }

    float4 bb = *reinterpret_cast<const float4*>(&bsh[lane * 4]);
#pragma unroll
    for (int p = 0; p < 8; p++) {
        float a0[4], a1[4];
#pragma unroll
        for (int c = 0; c < 4; c++) upk2(a0[c], a1[c], accP[p][c]);
#pragma unroll
        for (int half = 0; half < 2; half++) {
            int n = node0 + warp * 16 + 2 * p + half;
            if (n >= nN) continue;
            const float* av = half ? a1 : a0;
            float4 o;
            o.x = fmaxf(av[0] + bb.x, 0.f);
            o.y = fmaxf(av[1] + bb.y, 0.f);
            o.z = fmaxf(av[2] + bb.z, 0.f);
            o.w = fmaxf(av[3] + bb.w, 0.f);
            if (mode == 0) {
                float d = g_dis[n];
                __nv_bfloat162 p0 = __float22bfloat162_rn(make_float2(o.x * d, o.y * d));
                __nv_bfloat162 p1 = __float22bfloat162_rn(make_float2(o.z * d, o.w * d));
                uint2 u;
                u.x = *reinterpret_cast<unsigned*>(&p0);
                u.y = *reinterpret_cast<unsigned*>(&p1);
                reinterpret_cast<uint2*>(g_h1b)[(size_t)n * 32 + lane] = u;
            } else {
                int g = __ldg(&gid[n]);
                red_add_v4(reinterpret_cast<float4*>(&g_pooled[(size_t)g * DH]) + lane, o);
                if (lane == 0) atomicAdd(&g_cnt[g], 1.0f);
            }
        }
    }
}

// ---------------- classifier ----------------
__global__ void k_logits(const float* __restrict__ Wc, const float* __restrict__ bc,
                         float* __restrict__ out, int nG) {
    int t = threadIdx.x;      // 512 threads
    int g = t >> 3, c = t & 7;
    if (g >= nG) return;
    float s = 0.f;
#pragma unroll 8
    for (int k = 0; k < DH; k++)
        s = fmaf(g_pooled[g * DH + k], __ldg(&Wc[k * 8 + c]), s);
    float cnt = fmaxf(g_cnt[g], 1.0f);
    out[g * 8 + c] = s / cnt + bc[c];
}

// ---------------- launch ----------------
extern "C" void kernel_launch(void* const* d_in, const int* in_sizes, int n_in,
                              void* d_out, int out_size) {
    const float* x  = (const float*)d_in[0];
    const int*   ei = (const int*)  d_in[1];
    const int*   gid= (const int*)  d_in[2];
    const float* W1 = (const float*)d_in[3];
    const float* b1 = (const float*)d_in[4];
    const float* W2 = (const float*)d_in[5];
    const float* b2 = (const float*)d_in[6];
    const float* Wc = (const float*)d_in[7];
    const float* bc = (const float*)d_in[8];
    float* out = (float*)d_out;

    int nN = in_sizes[0] / DH;
    int nE = in_sizes[1] / 2;
    int nG = out_size / 8;
    const int* src = ei;
    const int* dst = ei + nE;

    const int T = 256;
    int gN16 = (int)(((long long)nN * 16 + T - 1) / T);
    int scaleBlocks = (int)(((long long)nN * 32 + T - 1) / T);
    int gGemm = (nN + NPB - 1) / NPB;

    // 1: histogram   2: scan (+count re-zero)   3: fused build + x pre-scale
    if ((nE & 3) == 0) {
        int nQ = nE >> 2;
        int Bb = (nQ + T - 1) / T;
        k_hist4<<<Bb, T>>>((const int4*)dst, nQ);
        k_scan<<<1, 1024>>>(nN);
        k_build_scale<<<Bb + scaleBlocks, T>>>((const int4*)src, (const int4*)dst,
                                               nQ, (const float4*)x, nN, Bb);
    } else {
        int Bb = (nE / 4 + T) / T;
        k_hist_s<<<Bb, T>>>(dst, nE);
        k_scan<<<1, 1024>>>(nN);
        k_build_scale_s<<<Bb + scaleBlocks, T>>>(src, dst, nE, (const float4*)x, nN, Bb);
    }

    // 4: layer-1 gather (profiled slot)   5: GEMM1 -> h1b
    k_gather<<<gN16, T>>>(1, nN);
    k_gemm_relu<<<gGemm, T>>>(W1, b1, gid, nN, 0);

    // 6: layer-2 gather   7: GEMM2 (+fused pooling)
    k_gather<<<gN16, T>>>(0, nN);
    k_gemm_relu<<<gGemm, T>>>(W2, b2, gid, nN, 1);

    // 8: classify
    k_logits<<<1, 512>>>(Wc, bc, out, nG);
}